// round 11
// baseline (speedup 1.0000x reference)
#include <cuda_runtime.h>
#include <cuda_bf16.h>
#include <cuda_fp16.h>
#include <cstdint>

#define NN 50000
#define EE 600000
#define HH 128
#define CAP 96
#define SLOPE 0.01f

// ---------------- scratch (static device globals; no allocation) ----------------
__device__ int   g_cnt[NN];
__device__ float g_dinv[NN];
__device__ int   g_slots[NN * CAP];
__device__ float g_bufA[NN * HH];     // also used as __half h buffer
__device__ float g_bufB[NN * HH];
__device__ float g_bufC[NN * HH];
__device__ __nv_bfloat16 g_whi[6 * HH * HH];
__device__ __nv_bfloat16 g_wlo[6 * HH * HH];

__device__ __forceinline__ float lrelu(float x) { return x >= 0.f ? x : SLOPE * x; }

// ---------------- bucket CSR build ----------------
__global__ void fill_kernel(const int* __restrict__ src, const int* __restrict__ dst) {
    int base = (blockIdx.x * blockDim.x + threadIdx.x) * 4;
#pragma unroll
    for (int j = 0; j < 4; j++) {
        int e = base + j;
        if (e < EE) {
            int s = src[e];
            int d = dst[e];
            int pos = atomicAdd(&g_cnt[d], 1);
            if (pos < CAP) g_slots[d * CAP + pos] = s;
        }
    }
}
__global__ void dinv_kernel() {
    int i = blockIdx.x * blockDim.x + threadIdx.x;
    if (i < NN) g_dinv[i] = rsqrtf((float)g_cnt[i] + 1.0f);
}

// ---------------- weight convert: all 6 layers, one launch ----------------
struct WPtrs { const float* p[6]; };
__global__ void wconv_all(WPtrs W) {
    int l = blockIdx.y;
    int idx = blockIdx.x * blockDim.x + threadIdx.x;
    if (idx >= HH * HH) return;
    int n = idx >> 7;
    int k = idx & 127;
    float v = W.p[l][k * HH + n];
    __nv_bfloat16 h = __float2bfloat16(v);
    __nv_bfloat16 lo = __float2bfloat16(v - __bfloat162float(h));
    g_whi[l * HH * HH + n * HH + k] = h;
    g_wlo[l * HH * HH + n * HH + k] = lo;
}

// ---------------- bucket gather (warp per node, fp16 h) ----------------
__global__ void gather_kernel(const __half* __restrict__ h,
                              const float* __restrict__ bias,
                              const float* __restrict__ prev,
                              float* __restrict__ out) {
    int node = (blockIdx.x * blockDim.x + threadIdx.x) >> 5;
    int lane = threadIdx.x & 31;
    if (node >= NN) return;
    int n = g_cnt[node];
    if (n > CAP) n = CAP;
    const int* sl = &g_slots[node * CAP];
    float4 acc = make_float4(0.f, 0.f, 0.f, 0.f);
    int j = 0;
    for (; j + 1 < n; j += 2) {
        int s0 = sl[j];
        int s1 = sl[j + 1];
        float w0 = g_dinv[s0];
        float w1 = g_dinv[s1];
        uint2 u0 = *(const uint2*)&h[s0 * HH + lane * 4];
        uint2 u1 = *(const uint2*)&h[s1 * HH + lane * 4];
        float2 a0 = __half22float2(*(__half2*)&u0.x);
        float2 b0 = __half22float2(*(__half2*)&u0.y);
        float2 a1 = __half22float2(*(__half2*)&u1.x);
        float2 b1 = __half22float2(*(__half2*)&u1.y);
        acc.x = fmaf(w0, a0.x, acc.x); acc.y = fmaf(w0, a0.y, acc.y);
        acc.z = fmaf(w0, b0.x, acc.z); acc.w = fmaf(w0, b0.y, acc.w);
        acc.x = fmaf(w1, a1.x, acc.x); acc.y = fmaf(w1, a1.y, acc.y);
        acc.z = fmaf(w1, b1.x, acc.z); acc.w = fmaf(w1, b1.y, acc.w);
    }
    if (j < n) {
        int s0 = sl[j];
        float w0 = g_dinv[s0];
        uint2 u0 = *(const uint2*)&h[s0 * HH + lane * 4];
        float2 a0 = __half22float2(*(__half2*)&u0.x);
        float2 b0 = __half22float2(*(__half2*)&u0.y);
        acc.x = fmaf(w0, a0.x, acc.x); acc.y = fmaf(w0, a0.y, acc.y);
        acc.z = fmaf(w0, b0.x, acc.z); acc.w = fmaf(w0, b0.y, acc.w);
    }
    float di = g_dinv[node];
    float d2 = di * di;
    uint2 us = *(const uint2*)&h[node * HH + lane * 4];
    float2 sa = __half22float2(*(__half2*)&us.x);
    float2 sb = __half22float2(*(__half2*)&us.y);
    float4 bv = *(const float4*)&bias[lane * 4];
    float4 r;
    r.x = fmaf(di, acc.x, fmaf(d2, sa.x, bv.x));
    r.y = fmaf(di, acc.y, fmaf(d2, sa.y, bv.y));
    r.z = fmaf(di, acc.z, fmaf(d2, sb.x, bv.z));
    r.w = fmaf(di, acc.w, fmaf(d2, sb.y, bv.w));
    if (prev) {
        float4 pv = *(const float4*)&prev[node * HH + lane * 4];
        r.x = lrelu(r.x + lrelu(pv.x));
        r.y = lrelu(r.y + lrelu(pv.y));
        r.z = lrelu(r.z + lrelu(pv.z));
        r.w = lrelu(r.w + lrelu(pv.w));
    }
    *(float4*)&out[node * HH + lane * 4] = r;
}

// ---------------- mma helpers ----------------
__device__ __forceinline__ uint32_t smem_u32(const void* p) {
    uint32_t a;
    asm("{ .reg .u64 t; cvta.to.shared.u64 t, %1; cvt.u32.u64 %0, t; }" : "=r"(a) : "l"(p));
    return a;
}
__device__ __forceinline__ void cp16(uint32_t saddr, const void* g) {
    asm volatile("cp.async.cg.shared.global [%0], [%1], 16;" :: "r"(saddr), "l"(g));
}
__device__ __forceinline__ void ldsm_x4(uint32_t r[4], uint32_t addr) {
    asm volatile("ldmatrix.sync.aligned.m8n8.x4.shared.b16 {%0,%1,%2,%3}, [%4];"
                 : "=r"(r[0]), "=r"(r[1]), "=r"(r[2]), "=r"(r[3]) : "r"(addr));
}
__device__ __forceinline__ void mma_bf16(float c[4], const uint32_t a[4], uint32_t b0, uint32_t b1) {
    asm volatile(
        "mma.sync.aligned.m16n8k16.row.col.f32.bf16.bf16.f32 "
        "{%0,%1,%2,%3}, {%4,%5,%6,%7}, {%8,%9}, {%0,%1,%2,%3};"
        : "+f"(c[0]), "+f"(c[1]), "+f"(c[2]), "+f"(c[3])
        : "r"(a[0]), "r"(a[1]), "r"(a[2]), "r"(a[3]), "r"(b0), "r"(b1));
}
__device__ __forceinline__ void split2(float v0, float v1, uint32_t& hw, uint32_t& lw) {
    __nv_bfloat16 h0 = __float2bfloat16(v0), h1 = __float2bfloat16(v1);
    __nv_bfloat16 l0 = __float2bfloat16(v0 - __bfloat162float(h0));
    __nv_bfloat16 l1 = __float2bfloat16(v1 - __bfloat162float(h1));
    __nv_bfloat162 hp = {h0, h1}, lp = {l0, l1};
    hw = *(uint32_t*)&hp;
    lw = *(uint32_t*)&lp;
}

// ---------------- simple 3-term MMA pass, warp tile 16x32 (TLP-reliant) ----------------
template<int AHO, int ALO, int WHO, int WLO>
__device__ __forceinline__ void mma_pass_16x32(
    uint32_t sb, uint32_t aoff_base, uint32_t axor, int acg,
    int wn, int bn_local, int bcg, float acc[4][4]) {
#pragma unroll
    for (int ks = 0; ks < 8; ks++) {
        const int kb = ks * 32;
        uint32_t ah[4], al[4];
        uint32_t a_addr = sb + aoff_base + (uint32_t)((kb + acg) ^ axor);
        ldsm_x4(ah, a_addr + AHO);
        ldsm_x4(al, a_addr + ALO);
#pragma unroll
        for (int p = 0; p < 2; p++) {
            const int nrow = wn * 32 + p * 16 + bn_local;
            uint32_t b_addr = sb + (uint32_t)(nrow * 256)
                            + (uint32_t)((kb + bcg) ^ ((nrow & 7) << 4));
            uint32_t bh[4], bl[4];
            ldsm_x4(bh, b_addr + WHO);
            ldsm_x4(bl, b_addr + WLO);
            mma_bf16(acc[2 * p],     ah, bh[0], bh[1]);
            mma_bf16(acc[2 * p + 1], ah, bh[2], bh[3]);
            mma_bf16(acc[2 * p],     al, bh[0], bh[1]);
            mma_bf16(acc[2 * p + 1], al, bh[2], bh[3]);
            mma_bf16(acc[2 * p],     ah, bl[0], bl[1]);
            mma_bf16(acc[2 * p + 1], ah, bl[2], bl[3]);
        }
    }
}

// ---------------- conv GEMM: M-tile 64, 512 thr, 96KB, warp tile 16x32, fp16 out ----------------
#define SA_H 0
#define SA_L 16384
#define SW_H 32768
#define SW_L 65536
#define GEMM_SMEM 98304

__global__ void __launch_bounds__(512, 2) mma_gemm_h(
    const float* __restrict__ A,
    const uint4* __restrict__ Wth, const uint4* __restrict__ Wtl,
    __half* __restrict__ C,
    int M, int mode) {
    extern __shared__ char smem[];
    const uint32_t sb = smem_u32(smem);
    const int tid = threadIdx.x;
    const int lane = tid & 31;
    const int wid = tid >> 5;
    const int wm = wid & 3;     // 4 M-blocks of 16
    const int wn = wid >> 2;    // 4 N-blocks of 32
    const int blockRow = blockIdx.x * 64;

    // W images via cp.async: 2048 uint4 per image, 4 iters @512 thr
#pragma unroll
    for (int i = 0; i < 4; i++) {
        int c = tid + i * 512;
        int n = c >> 4;
        int kb = (c & 15) * 16;
        uint32_t off = (uint32_t)(n * 256) + (uint32_t)(kb ^ ((n & 7) << 4));
        cp16(sb + SW_H + off, &Wth[c]);
        cp16(sb + SW_L + off, &Wtl[c]);
    }
    asm volatile("cp.async.commit_group;" ::: "memory");

    // A: 64 rows x 32 float4 = 2048 chunks, 4 iters
#pragma unroll
    for (int i = 0; i < 4; i++) {
        int idx = tid + i * 512;
        int row = idx >> 5;
        int col = (idx & 31) * 4;
        int grow = blockRow + row;
        float4 v = make_float4(0.f, 0.f, 0.f, 0.f);
        if (grow < M) v = *(const float4*)&A[grow * HH + col];
        if (mode & 32) { v.x = lrelu(v.x); v.y = lrelu(v.y); v.z = lrelu(v.z); v.w = lrelu(v.w); }
        uint32_t h0, l0, h1, l1;
        split2(v.x, v.y, h0, l0);
        split2(v.z, v.w, h1, l1);
        uint32_t off = (uint32_t)(row * 256) + (uint32_t)((col * 2) ^ ((row & 7) << 4));
        *(uint2*)(smem + SA_H + off) = make_uint2(h0, h1);
        *(uint2*)(smem + SA_L + off) = make_uint2(l0, l1);
    }
    asm volatile("cp.async.wait_group 0;" ::: "memory");
    __syncthreads();

    float acc[4][4];
#pragma unroll
    for (int j = 0; j < 4; j++)
#pragma unroll
        for (int q = 0; q < 4; q++) acc[j][q] = 0.f;

    const int arow = wm * 16 + (lane & 15);
    const int acg = (lane >> 4) * 16;
    const uint32_t aoff_base = (uint32_t)(arow * 256);
    const uint32_t axor = (uint32_t)((arow & 7) << 4);
    const int bn_local = (lane & 7) + ((lane >> 4) & 1) * 8;
    const int bcg = ((lane >> 3) & 1) * 16;

    mma_pass_16x32<SA_H, SA_L, SW_H, SW_L>(sb, aoff_base, axor, acg, wn, bn_local, bcg, acc);

    const int g = lane >> 2, t = lane & 3;
    int rr0 = blockRow + wm * 16 + g;
#pragma unroll
    for (int h = 0; h < 2; h++) {
        int row = rr0 + h * 8;
        if (row >= M) continue;
#pragma unroll
        for (int j = 0; j < 4; j++) {
            int col = wn * 32 + j * 8 + t * 2;
            *(__half2*)&C[row * HH + col] =
                __floats2half2_rn(acc[j][h * 2 + 0], acc[j][h * 2 + 1]);
        }
    }
}

// ---------------- 4-layer fused MLP: 512 thr, warp tile 16x32 ----------------
#define G_AH 0
#define G_AL 16384
#define G_WH 32768
#define G_WL 65536
#define G_SMEM 98304

struct MLP4Args {
    const uint4* wh[4];
    const uint4* wl[4];
    const float* b[4];
};

__global__ void __launch_bounds__(512, 2) mlp4(
    const float* __restrict__ A,     // h2 (also the residual)
    MLP4Args args,
    const float* __restrict__ gen,
    float* __restrict__ C,
    int M) {
    extern __shared__ char smem[];
    const uint32_t sb = smem_u32(smem);
    const int tid = threadIdx.x;
    const int lane = tid & 31;
    const int wid = tid >> 5;
    const int wm = wid & 3;
    const int wn = wid >> 2;
    const int blockRow = blockIdx.x * 64;

    // W0 via cp.async
#pragma unroll
    for (int i = 0; i < 4; i++) {
        int c = tid + i * 512;
        int n = c >> 4;
        int kb = (c & 15) * 16;
        uint32_t off = (uint32_t)(n * 256) + (uint32_t)(kb ^ ((n & 7) << 4));
        cp16(sb + G_WH + off, &args.wh[0][c]);
        cp16(sb + G_WL + off, &args.wl[0][c]);
    }
    asm volatile("cp.async.commit_group;" ::: "memory");

    // A: 64 rows x 32 float4, convert to bf16 hi/lo
#pragma unroll
    for (int i = 0; i < 4; i++) {
        int idx = tid + i * 512;
        int row = idx >> 5;
        int col = (idx & 31) * 4;
        int grow = blockRow + row;
        float4 v = make_float4(0.f, 0.f, 0.f, 0.f);
        if (grow < M) v = *(const float4*)&A[grow * HH + col];
        uint32_t h0, l0, h1, l1;
        split2(v.x, v.y, h0, l0);
        split2(v.z, v.w, h1, l1);
        uint32_t off = (uint32_t)(row * 256) + (uint32_t)((col * 2) ^ ((row & 7) << 4));
        *(uint2*)(smem + G_AH + off) = make_uint2(h0, h1);
        *(uint2*)(smem + G_AL + off) = make_uint2(l0, l1);
    }
    asm volatile("cp.async.wait_group 0;" ::: "memory");
    __syncthreads();

    const int arow = wm * 16 + (lane & 15);
    const int acg = (lane >> 4) * 16;
    const uint32_t aoff_base = (uint32_t)(arow * 256);
    const uint32_t axor = (uint32_t)((arow & 7) << 4);
    const int bn_local = (lane & 7) + ((lane >> 4) & 1) * 8;
    const int bcg = ((lane >> 3) & 1) * 16;
    const int g = lane >> 2, t = lane & 3;

    float acc[4][4];

#pragma unroll
    for (int layer = 0; layer < 4; layer++) {
#pragma unroll
        for (int j = 0; j < 4; j++)
#pragma unroll
            for (int q = 0; q < 4; q++) acc[j][q] = 0.f;
        mma_pass_16x32<G_AH, G_AL, G_WH, G_WL>(sb, aoff_base, axor, acg, wn, bn_local, bcg, acc);
        __syncthreads();   // all warps done reading W[layer] and A smem

        if (layer < 3) {
            // prefetch next layer's weights over the W region
#pragma unroll
            for (int i = 0; i < 4; i++) {
                int c = tid + i * 512;
                int n = c >> 4;
                int kb = (c & 15) * 16;
                uint32_t off = (uint32_t)(n * 256) + (uint32_t)(kb ^ ((n & 7) << 4));
                cp16(sb + G_WH + off, &args.wh[layer + 1][c]);
                cp16(sb + G_WL + off, &args.wl[layer + 1][c]);
            }
            asm volatile("cp.async.commit_group;" ::: "memory");
        }

        const float* bias = args.b[layer];
        if (layer == 3) {
            // final: leaky(acc + b) -> gmem
#pragma unroll
            for (int h = 0; h < 2; h++) {
                int row = blockRow + wm * 16 + g + h * 8;
                if (row >= M) continue;
#pragma unroll
                for (int j = 0; j < 4; j++) {
                    int col = wn * 32 + j * 8 + t * 2;
                    float v0 = lrelu(acc[j][h * 2 + 0] + bias[col]);
                    float v1 = lrelu(acc[j][h * 2 + 1] + bias[col + 1]);
                    *(float2*)&C[row * HH + col] = make_float2(v0, v1);
                }
            }
        } else {
            // intermediate epilogue -> back into A smem as bf16 hi/lo
#pragma unroll
            for (int h = 0; h < 2; h++) {
                int lrow = wm * 16 + g + h * 8;
                int grow = blockRow + lrow;
#pragma unroll
                for (int j = 0; j < 4; j++) {
                    int col = wn * 32 + j * 8 + t * 2;
                    float v0 = acc[j][h * 2 + 0] + bias[col];
                    float v1 = acc[j][h * 2 + 1] + bias[col + 1];
                    if (layer == 1) {
                        float2 rv = (grow < M) ? *(const float2*)&A[grow * HH + col]
                                               : make_float2(0.f, 0.f);
                        v0 = lrelu(v0 + rv.x);
                        v1 = lrelu(v1 + rv.y);
                        float2 gv = (grow < M) ? *(const float2*)&gen[grow * HH + col]
                                               : make_float2(0.f, 0.f);
                        v0 = 0.5f * v0 + 0.5f * gv.x;
                        v1 = 0.5f * v1 + 0.5f * gv.y;
                    } else {
                        v0 = lrelu(v0);
                        v1 = lrelu(v1);
                    }
                    uint32_t hw, lw;
                    split2(v0, v1, hw, lw);
                    uint32_t off = (uint32_t)(lrow * 256) + (uint32_t)((col * 2) ^ ((lrow & 7) << 4));
                    *(uint32_t*)(smem + G_AH + off) = hw;
                    *(uint32_t*)(smem + G_AL + off) = lw;
                }
            }
            asm volatile("cp.async.wait_group 0;" ::: "memory");
            __syncthreads();
        }
    }
}

// ---------------- launch ----------------
extern "C" void kernel_launch(void* const* d_in, const int* in_sizes, int n_in,
                              void* d_out, int out_size) {
    const float* x   = (const float*)d_in[0];
    const int*   ei  = (const int*)d_in[1];
    const float* gen = (const float*)d_in[2];
    const float* Wc1 = (const float*)d_in[3];
    const float* bc1 = (const float*)d_in[4];
    const float* Wc2 = (const float*)d_in[5];
    const float* bc2 = (const float*)d_in[6];
    const float* Wm1 = (const float*)d_in[7];
    const float* bm1 = (const float*)d_in[8];
    const float* Wm2 = (const float*)d_in[9];
    const float* bm2 = (const float*)d_in[10];
    const float* Wp1 = (const float*)d_in[11];
    const float* bp1 = (const float*)d_in[12];
    const float* Wp2 = (const float*)d_in[13];
    const float* bp2 = (const float*)d_in[14];

    const int* src = ei;
    const int* dst = ei + EE;

    float *bufA, *bufB, *bufC;
    __nv_bfloat16 *whi, *wlo;
    int* cntp;
    cudaGetSymbolAddress((void**)&bufA, g_bufA);
    cudaGetSymbolAddress((void**)&bufB, g_bufB);
    cudaGetSymbolAddress((void**)&bufC, g_bufC);
    cudaGetSymbolAddress((void**)&whi, g_whi);
    cudaGetSymbolAddress((void**)&wlo, g_wlo);
    cudaGetSymbolAddress((void**)&cntp, g_cnt);

    static bool s_init = false;
    static cudaStream_t s_side;
    static cudaEvent_t ev_fork, ev_join;
    if (!s_init) {
        cudaStreamCreateWithFlags(&s_side, cudaStreamNonBlocking);
        cudaEventCreateWithFlags(&ev_fork, cudaEventDisableTiming);
        cudaEventCreateWithFlags(&ev_join, cudaEventDisableTiming);
        cudaFuncSetAttribute(mma_gemm_h, cudaFuncAttributeMaxDynamicSharedMemorySize, GEMM_SMEM);
        cudaFuncSetAttribute(mlp4, cudaFuncAttributeMaxDynamicSharedMemorySize, G_SMEM);
        s_init = true;
    }

    const int gE4 = (EE / 4 + 255) / 256;
    const int gN = (NN + 255) / 256;
    const int gGat = (NN * 32 + 255) / 256;   // warp per node
    const int gG = (NN + 63) / 64;            // M=64 tiles

    const uint4* w4hi = (const uint4*)whi;
    const uint4* w4lo = (const uint4*)wlo;
    const int WSTEP = HH * HH / 8;
    __half* hbuf = (__half*)bufA;

    WPtrs wp;
    wp.p[0] = Wc1; wp.p[1] = Wc2; wp.p[2] = Wm1;
    wp.p[3] = Wm2; wp.p[4] = Wp1; wp.p[5] = Wp2;
    dim3 wgrid((HH * HH + 255) / 256, 6);

    // fork: CSR build on side stream (hidden under wconv + conv1)
    cudaMemsetAsync(cntp, 0, NN * sizeof(int));
    cudaEventRecord(ev_fork, 0);
    cudaStreamWaitEvent(s_side, ev_fork, 0);
    fill_kernel<<<gE4, 256, 0, s_side>>>(src, dst);
    dinv_kernel<<<gN, 256, 0, s_side>>>();
    cudaEventRecord(ev_join, s_side);

    // main: weights + conv1 GEMM (independent of CSR)
    wconv_all<<<wgrid, 256>>>(wp);
    mma_gemm_h<<<gG, 512, GEMM_SMEM>>>(x, w4hi, w4lo, hbuf, NN, 0);

    // join: gather needs CSR
    cudaStreamWaitEvent(0, ev_join, 0);
    gather_kernel<<<gGat, 256>>>(hbuf, bc1, nullptr, bufB);

    // conv2
    mma_gemm_h<<<gG, 512, GEMM_SMEM>>>(bufB, w4hi + WSTEP, w4lo + WSTEP, hbuf, NN, 32);
    gather_kernel<<<gGat, 256>>>(hbuf, bc2, bufB, bufC);

    // 4-layer fused MLP + proj -> out
    MLP4Args ma;
    ma.wh[0] = w4hi + 2 * WSTEP; ma.wl[0] = w4lo + 2 * WSTEP; ma.b[0] = bm1;
    ma.wh[1] = w4hi + 3 * WSTEP; ma.wl[1] = w4lo + 3 * WSTEP; ma.b[1] = bm2;
    ma.wh[2] = w4hi + 4 * WSTEP; ma.wl[2] = w4lo + 4 * WSTEP; ma.b[2] = bp1;
    ma.wh[3] = w4hi + 5 * WSTEP; ma.wl[3] = w4lo + 5 * WSTEP; ma.b[3] = bp2;
    mlp4<<<gG, 512, G_SMEM>>>(bufC, ma, gen, (float*)d_out, NN);
}

// round 12
// speedup vs baseline: 1.2058x; 1.2058x over previous
#include <cuda_runtime.h>
#include <cuda_bf16.h>
#include <cuda_fp16.h>
#include <cstdint>

#define NN 50000
#define EE 600000
#define HH 128
#define CAP 96
#define SLOPE 0.01f

// ---------------- scratch (static device globals; no allocation) ----------------
__device__ int   g_cnt[NN];
__device__ float g_dinv[NN];
__device__ int   g_slots[NN * CAP];
__device__ float g_bufA[NN * HH];     // also used as __half h buffer
__device__ float g_bufB[NN * HH];
__device__ float g_bufC[NN * HH];
__device__ __half g_wh[6 * HH * HH];  // single fp16 n-major weight images

__device__ __forceinline__ float lrelu(float x) { return x >= 0.f ? x : SLOPE * x; }

// ---------------- bucket CSR build ----------------
__global__ void fill_kernel(const int* __restrict__ src, const int* __restrict__ dst) {
    int base = (blockIdx.x * blockDim.x + threadIdx.x) * 4;
#pragma unroll
    for (int j = 0; j < 4; j++) {
        int e = base + j;
        if (e < EE) {
            int s = src[e];
            int d = dst[e];
            int pos = atomicAdd(&g_cnt[d], 1);
            if (pos < CAP) g_slots[d * CAP + pos] = s;
        }
    }
}
__global__ void dinv_kernel() {
    int i = blockIdx.x * blockDim.x + threadIdx.x;
    if (i < NN) g_dinv[i] = rsqrtf((float)g_cnt[i] + 1.0f);
}

// ---------------- weight convert: all 6 layers, one launch, fp16 ----------------
struct WPtrs { const float* p[6]; };
__global__ void wconv_all(WPtrs W) {
    int l = blockIdx.y;
    int idx = blockIdx.x * blockDim.x + threadIdx.x;
    if (idx >= HH * HH) return;
    int n = idx >> 7;
    int k = idx & 127;
    g_wh[l * HH * HH + n * HH + k] = __float2half_rn(W.p[l][k * HH + n]);
}

// ---------------- bucket gather (warp per node, fp16 h) ----------------
__global__ void gather_kernel(const __half* __restrict__ h,
                              const float* __restrict__ bias,
                              const float* __restrict__ prev,
                              float* __restrict__ out) {
    int node = (blockIdx.x * blockDim.x + threadIdx.x) >> 5;
    int lane = threadIdx.x & 31;
    if (node >= NN) return;
    int n = g_cnt[node];
    if (n > CAP) n = CAP;
    const int* sl = &g_slots[node * CAP];
    float4 acc = make_float4(0.f, 0.f, 0.f, 0.f);
    int j = 0;
    for (; j + 1 < n; j += 2) {
        int s0 = sl[j];
        int s1 = sl[j + 1];
        float w0 = g_dinv[s0];
        float w1 = g_dinv[s1];
        uint2 u0 = *(const uint2*)&h[s0 * HH + lane * 4];
        uint2 u1 = *(const uint2*)&h[s1 * HH + lane * 4];
        float2 a0 = __half22float2(*(__half2*)&u0.x);
        float2 b0 = __half22float2(*(__half2*)&u0.y);
        float2 a1 = __half22float2(*(__half2*)&u1.x);
        float2 b1 = __half22float2(*(__half2*)&u1.y);
        acc.x = fmaf(w0, a0.x, acc.x); acc.y = fmaf(w0, a0.y, acc.y);
        acc.z = fmaf(w0, b0.x, acc.z); acc.w = fmaf(w0, b0.y, acc.w);
        acc.x = fmaf(w1, a1.x, acc.x); acc.y = fmaf(w1, a1.y, acc.y);
        acc.z = fmaf(w1, b1.x, acc.z); acc.w = fmaf(w1, b1.y, acc.w);
    }
    if (j < n) {
        int s0 = sl[j];
        float w0 = g_dinv[s0];
        uint2 u0 = *(const uint2*)&h[s0 * HH + lane * 4];
        float2 a0 = __half22float2(*(__half2*)&u0.x);
        float2 b0 = __half22float2(*(__half2*)&u0.y);
        acc.x = fmaf(w0, a0.x, acc.x); acc.y = fmaf(w0, a0.y, acc.y);
        acc.z = fmaf(w0, b0.x, acc.z); acc.w = fmaf(w0, b0.y, acc.w);
    }
    float di = g_dinv[node];
    float d2 = di * di;
    uint2 us = *(const uint2*)&h[node * HH + lane * 4];
    float2 sa = __half22float2(*(__half2*)&us.x);
    float2 sb = __half22float2(*(__half2*)&us.y);
    float4 bv = *(const float4*)&bias[lane * 4];
    float4 r;
    r.x = fmaf(di, acc.x, fmaf(d2, sa.x, bv.x));
    r.y = fmaf(di, acc.y, fmaf(d2, sa.y, bv.y));
    r.z = fmaf(di, acc.z, fmaf(d2, sb.x, bv.z));
    r.w = fmaf(di, acc.w, fmaf(d2, sb.y, bv.w));
    if (prev) {
        float4 pv = *(const float4*)&prev[node * HH + lane * 4];
        r.x = lrelu(r.x + lrelu(pv.x));
        r.y = lrelu(r.y + lrelu(pv.y));
        r.z = lrelu(r.z + lrelu(pv.z));
        r.w = lrelu(r.w + lrelu(pv.w));
    }
    *(float4*)&out[node * HH + lane * 4] = r;
}

// ---------------- mma helpers ----------------
__device__ __forceinline__ uint32_t smem_u32(const void* p) {
    uint32_t a;
    asm("{ .reg .u64 t; cvta.to.shared.u64 t, %1; cvt.u32.u64 %0, t; }" : "=r"(a) : "l"(p));
    return a;
}
__device__ __forceinline__ void cp16(uint32_t saddr, const void* g) {
    asm volatile("cp.async.cg.shared.global [%0], [%1], 16;" :: "r"(saddr), "l"(g));
}
__device__ __forceinline__ void ldsm_x4(uint32_t r[4], uint32_t addr) {
    asm volatile("ldmatrix.sync.aligned.m8n8.x4.shared.b16 {%0,%1,%2,%3}, [%4];"
                 : "=r"(r[0]), "=r"(r[1]), "=r"(r[2]), "=r"(r[3]) : "r"(addr));
}
__device__ __forceinline__ void mma_f16(float c[4], const uint32_t a[4], uint32_t b0, uint32_t b1) {
    asm volatile(
        "mma.sync.aligned.m16n8k16.row.col.f32.f16.f16.f32 "
        "{%0,%1,%2,%3}, {%4,%5,%6,%7}, {%8,%9}, {%0,%1,%2,%3};"
        : "+f"(c[0]), "+f"(c[1]), "+f"(c[2]), "+f"(c[3])
        : "r"(a[0]), "r"(a[1]), "r"(a[2]), "r"(a[3]), "r"(b0), "r"(b1));
}
// split fp32 -> fp16 hi/lo pair words (hi+lo exact to ~2^-22)
__device__ __forceinline__ void split2h(float v0, float v1, uint32_t& hw, uint32_t& lw) {
    __half h0 = __float2half_rn(v0), h1 = __float2half_rn(v1);
    __half l0 = __float2half_rn(v0 - __half2float(h0));
    __half l1 = __float2half_rn(v1 - __half2float(h1));
    __half2 hp = {h0, h1}, lp = {l0, l1};
    hw = *(uint32_t*)&hp;
    lw = *(uint32_t*)&lp;
}

// ---------------- 2-term MMA pass, warp tile 16x64: D = Ah*W + Al*W ----------------
template<int AHO, int ALO, int WO>
__device__ __forceinline__ void mma_pass2(
    uint32_t sb, uint32_t aoff_base, uint32_t axor, int acg,
    int wn, int bn_local, int bcg, float acc[8][4]) {
#pragma unroll
    for (int ks = 0; ks < 8; ks++) {
        const int kb = ks * 32;
        uint32_t ah[4], al[4];
        uint32_t a_addr = sb + aoff_base + (uint32_t)((kb + acg) ^ axor);
        ldsm_x4(ah, a_addr + AHO);
        ldsm_x4(al, a_addr + ALO);
#pragma unroll
        for (int p = 0; p < 4; p++) {
            const int nrow = wn * 64 + p * 16 + bn_local;
            uint32_t b_addr = sb + (uint32_t)(nrow * 256)
                            + (uint32_t)((kb + bcg) ^ ((nrow & 7) << 4));
            uint32_t bh[4];
            ldsm_x4(bh, b_addr + WO);
            mma_f16(acc[2 * p],     ah, bh[0], bh[1]);
            mma_f16(acc[2 * p + 1], ah, bh[2], bh[3]);
            mma_f16(acc[2 * p],     al, bh[0], bh[1]);
            mma_f16(acc[2 * p + 1], al, bh[2], bh[3]);
        }
    }
}

// ---------------- conv GEMM: M-tile 64, 256 thr, 64KB smem, fp16 out ----------------
#define SA_H 0
#define SA_L 16384
#define SW_W 32768
#define GEMM_SMEM 65536

__global__ void __launch_bounds__(256, 3) mma_gemm_h(
    const float* __restrict__ A,
    const uint4* __restrict__ Wt,
    __half* __restrict__ C,
    int M, int mode) {
    extern __shared__ char smem[];
    const uint32_t sb = smem_u32(smem);
    const int tid = threadIdx.x;
    const int lane = tid & 31;
    const int wid = tid >> 5;
    const int wm = wid & 3;     // 4 M-blocks of 16
    const int wn = wid >> 2;    // 2 N-blocks of 64
    const int blockRow = blockIdx.x * 64;

    // W image via cp.async: 2048 uint4, 8 iters
#pragma unroll
    for (int i = 0; i < 8; i++) {
        int c = tid + i * 256;
        int n = c >> 4;
        int kb = (c & 15) * 16;
        uint32_t off = (uint32_t)(n * 256) + (uint32_t)(kb ^ ((n & 7) << 4));
        cp16(sb + SW_W + off, &Wt[c]);
    }
    asm volatile("cp.async.commit_group;" ::: "memory");

    // A: 64 rows x 32 float4, convert fp32 -> fp16 hi/lo
#pragma unroll
    for (int i = 0; i < 8; i++) {
        int idx = tid + i * 256;
        int row = idx >> 5;
        int col = (idx & 31) * 4;
        int grow = blockRow + row;
        float4 v = make_float4(0.f, 0.f, 0.f, 0.f);
        if (grow < M) v = *(const float4*)&A[grow * HH + col];
        if (mode & 32) { v.x = lrelu(v.x); v.y = lrelu(v.y); v.z = lrelu(v.z); v.w = lrelu(v.w); }
        uint32_t h0, l0, h1, l1;
        split2h(v.x, v.y, h0, l0);
        split2h(v.z, v.w, h1, l1);
        uint32_t off = (uint32_t)(row * 256) + (uint32_t)((col * 2) ^ ((row & 7) << 4));
        *(uint2*)(smem + SA_H + off) = make_uint2(h0, h1);
        *(uint2*)(smem + SA_L + off) = make_uint2(l0, l1);
    }
    asm volatile("cp.async.wait_group 0;" ::: "memory");
    __syncthreads();

    float acc[8][4];
#pragma unroll
    for (int j = 0; j < 8; j++)
#pragma unroll
        for (int q = 0; q < 4; q++) acc[j][q] = 0.f;

    const int arow = wm * 16 + (lane & 15);
    const int acg = (lane >> 4) * 16;
    const uint32_t aoff_base = (uint32_t)(arow * 256);
    const uint32_t axor = (uint32_t)((arow & 7) << 4);
    const int bn_local = (lane & 7) + ((lane >> 4) & 1) * 8;
    const int bcg = ((lane >> 3) & 1) * 16;

    mma_pass2<SA_H, SA_L, SW_W>(sb, aoff_base, axor, acg, wn, bn_local, bcg, acc);

    const int g = lane >> 2, t = lane & 3;
    int rr0 = blockRow + wm * 16 + g;
#pragma unroll
    for (int h = 0; h < 2; h++) {
        int row = rr0 + h * 8;
        if (row >= M) continue;
#pragma unroll
        for (int j = 0; j < 8; j++) {
            int col = wn * 64 + j * 8 + t * 2;
            *(__half2*)&C[row * HH + col] =
                __floats2half2_rn(acc[j][h * 2 + 0], acc[j][h * 2 + 1]);
        }
    }
}

// ---------------- 4-layer fused MLP: 256 thr, 64KB, W region reloaded per layer ----------------
#define G_AH 0
#define G_AL 16384
#define G_W  32768
#define G_SMEM 65536

struct MLP4Args {
    const uint4* w[4];
    const float* b[4];
};

__global__ void __launch_bounds__(256, 3) mlp4(
    const float* __restrict__ A,     // h2 (also the residual)
    MLP4Args args,
    const float* __restrict__ gen,
    float* __restrict__ C,
    int M) {
    extern __shared__ char smem[];
    const uint32_t sb = smem_u32(smem);
    const int tid = threadIdx.x;
    const int lane = tid & 31;
    const int wid = tid >> 5;
    const int wm = wid & 3;
    const int wn = wid >> 2;
    const int blockRow = blockIdx.x * 64;

    // W0 via cp.async
#pragma unroll
    for (int i = 0; i < 8; i++) {
        int c = tid + i * 256;
        int n = c >> 4;
        int kb = (c & 15) * 16;
        uint32_t off = (uint32_t)(n * 256) + (uint32_t)(kb ^ ((n & 7) << 4));
        cp16(sb + G_W + off, &args.w[0][c]);
    }
    asm volatile("cp.async.commit_group;" ::: "memory");

    // A: 64 rows x 32 float4, convert to fp16 hi/lo
#pragma unroll
    for (int i = 0; i < 8; i++) {
        int idx = tid + i * 256;
        int row = idx >> 5;
        int col = (idx & 31) * 4;
        int grow = blockRow + row;
        float4 v = make_float4(0.f, 0.f, 0.f, 0.f);
        if (grow < M) v = *(const float4*)&A[grow * HH + col];
        uint32_t h0, l0, h1, l1;
        split2h(v.x, v.y, h0, l0);
        split2h(v.z, v.w, h1, l1);
        uint32_t off = (uint32_t)(row * 256) + (uint32_t)((col * 2) ^ ((row & 7) << 4));
        *(uint2*)(smem + G_AH + off) = make_uint2(h0, h1);
        *(uint2*)(smem + G_AL + off) = make_uint2(l0, l1);
    }
    asm volatile("cp.async.wait_group 0;" ::: "memory");
    __syncthreads();

    const int arow = wm * 16 + (lane & 15);
    const int acg = (lane >> 4) * 16;
    const uint32_t aoff_base = (uint32_t)(arow * 256);
    const uint32_t axor = (uint32_t)((arow & 7) << 4);
    const int bn_local = (lane & 7) + ((lane >> 4) & 1) * 8;
    const int bcg = ((lane >> 3) & 1) * 16;
    const int g = lane >> 2, t = lane & 3;

    float acc[8][4];

#pragma unroll
    for (int layer = 0; layer < 4; layer++) {
#pragma unroll
        for (int j = 0; j < 8; j++)
#pragma unroll
            for (int q = 0; q < 4; q++) acc[j][q] = 0.f;
        mma_pass2<G_AH, G_AL, G_W>(sb, aoff_base, axor, acg, wn, bn_local, bcg, acc);
        __syncthreads();   // all warps done reading W[layer] and A smem

        if (layer < 3) {
            // prefetch next layer's weights over the W region
#pragma unroll
            for (int i = 0; i < 8; i++) {
                int c = tid + i * 256;
                int n = c >> 4;
                int kb = (c & 15) * 16;
                uint32_t off = (uint32_t)(n * 256) + (uint32_t)(kb ^ ((n & 7) << 4));
                cp16(sb + G_W + off, &args.w[layer + 1][c]);
            }
            asm volatile("cp.async.commit_group;" ::: "memory");
        }

        const float* bias = args.b[layer];
        if (layer == 3) {
            // final: leaky(acc + b) -> gmem
#pragma unroll
            for (int h = 0; h < 2; h++) {
                int row = blockRow + wm * 16 + g + h * 8;
                if (row >= M) continue;
#pragma unroll
                for (int j = 0; j < 8; j++) {
                    int col = wn * 64 + j * 8 + t * 2;
                    float v0 = lrelu(acc[j][h * 2 + 0] + bias[col]);
                    float v1 = lrelu(acc[j][h * 2 + 1] + bias[col + 1]);
                    *(float2*)&C[row * HH + col] = make_float2(v0, v1);
                }
            }
        } else {
            // intermediate epilogue -> back into A smem as fp16 hi/lo
#pragma unroll
            for (int h = 0; h < 2; h++) {
                int lrow = wm * 16 + g + h * 8;
                int grow = blockRow + lrow;
#pragma unroll
                for (int j = 0; j < 8; j++) {
                    int col = wn * 64 + j * 8 + t * 2;
                    float v0 = acc[j][h * 2 + 0] + bias[col];
                    float v1 = acc[j][h * 2 + 1] + bias[col + 1];
                    if (layer == 1) {
                        float2 rv = (grow < M) ? *(const float2*)&A[grow * HH + col]
                                               : make_float2(0.f, 0.f);
                        v0 = lrelu(v0 + rv.x);
                        v1 = lrelu(v1 + rv.y);
                        float2 gv = (grow < M) ? *(const float2*)&gen[grow * HH + col]
                                               : make_float2(0.f, 0.f);
                        v0 = 0.5f * v0 + 0.5f * gv.x;
                        v1 = 0.5f * v1 + 0.5f * gv.y;
                    } else {
                        v0 = lrelu(v0);
                        v1 = lrelu(v1);
                    }
                    uint32_t hw, lw;
                    split2h(v0, v1, hw, lw);
                    uint32_t off = (uint32_t)(lrow * 256) + (uint32_t)((col * 2) ^ ((lrow & 7) << 4));
                    *(uint32_t*)(smem + G_AH + off) = hw;
                    *(uint32_t*)(smem + G_AL + off) = lw;
                }
            }
            asm volatile("cp.async.wait_group 0;" ::: "memory");
            __syncthreads();
        }
    }
}

// ---------------- launch ----------------
extern "C" void kernel_launch(void* const* d_in, const int* in_sizes, int n_in,
                              void* d_out, int out_size) {
    const float* x   = (const float*)d_in[0];
    const int*   ei  = (const int*)d_in[1];
    const float* gen = (const float*)d_in[2];
    const float* Wc1 = (const float*)d_in[3];
    const float* bc1 = (const float*)d_in[4];
    const float* Wc2 = (const float*)d_in[5];
    const float* bc2 = (const float*)d_in[6];
    const float* Wm1 = (const float*)d_in[7];
    const float* bm1 = (const float*)d_in[8];
    const float* Wm2 = (const float*)d_in[9];
    const float* bm2 = (const float*)d_in[10];
    const float* Wp1 = (const float*)d_in[11];
    const float* bp1 = (const float*)d_in[12];
    const float* Wp2 = (const float*)d_in[13];
    const float* bp2 = (const float*)d_in[14];

    const int* src = ei;
    const int* dst = ei + EE;

    float *bufA, *bufB, *bufC;
    __half* wh;
    int* cntp;
    cudaGetSymbolAddress((void**)&bufA, g_bufA);
    cudaGetSymbolAddress((void**)&bufB, g_bufB);
    cudaGetSymbolAddress((void**)&bufC, g_bufC);
    cudaGetSymbolAddress((void**)&wh, g_wh);
    cudaGetSymbolAddress((void**)&cntp, g_cnt);

    static bool s_init = false;
    static cudaStream_t s_side;
    static cudaEvent_t ev_fork, ev_join;
    if (!s_init) {
        cudaStreamCreateWithFlags(&s_side, cudaStreamNonBlocking);
        cudaEventCreateWithFlags(&ev_fork, cudaEventDisableTiming);
        cudaEventCreateWithFlags(&ev_join, cudaEventDisableTiming);
        cudaFuncSetAttribute(mma_gemm_h, cudaFuncAttributeMaxDynamicSharedMemorySize, GEMM_SMEM);
        cudaFuncSetAttribute(mlp4, cudaFuncAttributeMaxDynamicSharedMemorySize, G_SMEM);
        s_init = true;
    }

    const int gE4 = (EE / 4 + 255) / 256;
    const int gN = (NN + 255) / 256;
    const int gGat = (NN * 32 + 255) / 256;   // warp per node
    const int gG = (NN + 63) / 64;            // M=64 tiles

    const uint4* w4 = (const uint4*)wh;
    const int WSTEP = HH * HH / 8;            // uint4 per fp16 layer image
    __half* hbuf = (__half*)bufA;

    WPtrs wp;
    wp.p[0] = Wc1; wp.p[1] = Wc2; wp.p[2] = Wm1;
    wp.p[3] = Wm2; wp.p[4] = Wp1; wp.p[5] = Wp2;
    dim3 wgrid((HH * HH + 255) / 256, 6);

    // fork: CSR build on side stream (hidden under wconv + conv1)
    cudaMemsetAsync(cntp, 0, NN * sizeof(int));
    cudaEventRecord(ev_fork, 0);
    cudaStreamWaitEvent(s_side, ev_fork, 0);
    fill_kernel<<<gE4, 256, 0, s_side>>>(src, dst);
    dinv_kernel<<<gN, 256, 0, s_side>>>();
    cudaEventRecord(ev_join, s_side);

    // main: weights + conv1 GEMM (independent of CSR)
    wconv_all<<<wgrid, 256>>>(wp);
    mma_gemm_h<<<gG, 256, GEMM_SMEM>>>(x, w4, hbuf, NN, 0);

    // join: gather needs CSR
    cudaStreamWaitEvent(0, ev_join, 0);
    gather_kernel<<<gGat, 256>>>(hbuf, bc1, nullptr, bufB);

    // conv2
    mma_gemm_h<<<gG, 256, GEMM_SMEM>>>(bufB, w4 + WSTEP, hbuf, NN, 32);
    gather_kernel<<<gGat, 256>>>(hbuf, bc2, bufB, bufC);

    // 4-layer fused MLP + proj -> out
    MLP4Args ma;
    ma.w[0] = w4 + 2 * WSTEP; ma.b[0] = bm1;
    ma.w[1] = w4 + 3 * WSTEP; ma.b[1] = bm2;
    ma.w[2] = w4 + 4 * WSTEP; ma.b[2] = bp1;
    ma.w[3] = w4 + 5 * WSTEP; ma.b[3] = bp2;
    mlp4<<<gG, 256, G_SMEM>>>(bufC, ma, gen, (float*)d_out, NN);
}

// round 13
// speedup vs baseline: 1.3270x; 1.1005x over previous
#include <cuda_runtime.h>
#include <cuda_bf16.h>
#include <cuda_fp16.h>
#include <cstdint>

#define NN 50000
#define EE 600000
#define HH 128
#define CAP 96
#define SLOPE 0.01f

// ---------------- scratch (static device globals; no allocation) ----------------
__device__ int   g_cnt[NN];
__device__ float g_dinv[NN];
__device__ int   g_slots[NN * CAP];
__device__ float g_bufA[NN * HH];     // also used as __half h buffer
__device__ float g_bufB[NN * HH];
__device__ float g_bufC[NN * HH];
__device__ __half g_wh[6 * HH * HH];  // single fp16 n-major weight images

__device__ __forceinline__ float lrelu(float x) { return x >= 0.f ? x : SLOPE * x; }

// ---------------- bucket CSR build ----------------
__global__ void fill_kernel(const int* __restrict__ src, const int* __restrict__ dst) {
    int base = (blockIdx.x * blockDim.x + threadIdx.x) * 4;
#pragma unroll
    for (int j = 0; j < 4; j++) {
        int e = base + j;
        if (e < EE) {
            int s = src[e];
            int d = dst[e];
            int pos = atomicAdd(&g_cnt[d], 1);
            if (pos < CAP) g_slots[d * CAP + pos] = s;
        }
    }
}
__global__ void dinv_kernel() {
    int i = blockIdx.x * blockDim.x + threadIdx.x;
    if (i < NN) g_dinv[i] = rsqrtf((float)g_cnt[i] + 1.0f);
}

// ---------------- weight convert: all 6 layers, one launch, fp16 ----------------
struct WPtrs { const float* p[6]; };
__global__ void wconv_all(WPtrs W) {
    int l = blockIdx.y;
    int idx = blockIdx.x * blockDim.x + threadIdx.x;
    if (idx >= HH * HH) return;
    int n = idx >> 7;
    int k = idx & 127;
    g_wh[l * HH * HH + n * HH + k] = __float2half_rn(W.p[l][k * HH + n]);
}

// ---------------- bucket gather (warp per node, fp16 h) ----------------
__global__ void gather_kernel(const __half* __restrict__ h,
                              const float* __restrict__ bias,
                              const float* __restrict__ prev,
                              float* __restrict__ out) {
    int node = (blockIdx.x * blockDim.x + threadIdx.x) >> 5;
    int lane = threadIdx.x & 31;
    if (node >= NN) return;
    int n = g_cnt[node];
    if (n > CAP) n = CAP;
    const int* sl = &g_slots[node * CAP];
    float4 acc = make_float4(0.f, 0.f, 0.f, 0.f);
    int j = 0;
    for (; j + 1 < n; j += 2) {
        int s0 = sl[j];
        int s1 = sl[j + 1];
        float w0 = g_dinv[s0];
        float w1 = g_dinv[s1];
        uint2 u0 = *(const uint2*)&h[s0 * HH + lane * 4];
        uint2 u1 = *(const uint2*)&h[s1 * HH + lane * 4];
        float2 a0 = __half22float2(*(__half2*)&u0.x);
        float2 b0 = __half22float2(*(__half2*)&u0.y);
        float2 a1 = __half22float2(*(__half2*)&u1.x);
        float2 b1 = __half22float2(*(__half2*)&u1.y);
        acc.x = fmaf(w0, a0.x, acc.x); acc.y = fmaf(w0, a0.y, acc.y);
        acc.z = fmaf(w0, b0.x, acc.z); acc.w = fmaf(w0, b0.y, acc.w);
        acc.x = fmaf(w1, a1.x, acc.x); acc.y = fmaf(w1, a1.y, acc.y);
        acc.z = fmaf(w1, b1.x, acc.z); acc.w = fmaf(w1, b1.y, acc.w);
    }
    if (j < n) {
        int s0 = sl[j];
        float w0 = g_dinv[s0];
        uint2 u0 = *(const uint2*)&h[s0 * HH + lane * 4];
        float2 a0 = __half22float2(*(__half2*)&u0.x);
        float2 b0 = __half22float2(*(__half2*)&u0.y);
        acc.x = fmaf(w0, a0.x, acc.x); acc.y = fmaf(w0, a0.y, acc.y);
        acc.z = fmaf(w0, b0.x, acc.z); acc.w = fmaf(w0, b0.y, acc.w);
    }
    float di = g_dinv[node];
    float d2 = di * di;
    uint2 us = *(const uint2*)&h[node * HH + lane * 4];
    float2 sa = __half22float2(*(__half2*)&us.x);
    float2 sb = __half22float2(*(__half2*)&us.y);
    float4 bv = *(const float4*)&bias[lane * 4];
    float4 r;
    r.x = fmaf(di, acc.x, fmaf(d2, sa.x, bv.x));
    r.y = fmaf(di, acc.y, fmaf(d2, sa.y, bv.y));
    r.z = fmaf(di, acc.z, fmaf(d2, sb.x, bv.z));
    r.w = fmaf(di, acc.w, fmaf(d2, sb.y, bv.w));
    if (prev) {
        float4 pv = *(const float4*)&prev[node * HH + lane * 4];
        r.x = lrelu(r.x + lrelu(pv.x));
        r.y = lrelu(r.y + lrelu(pv.y));
        r.z = lrelu(r.z + lrelu(pv.z));
        r.w = lrelu(r.w + lrelu(pv.w));
    }
    *(float4*)&out[node * HH + lane * 4] = r;
}

// ---------------- mma helpers ----------------
__device__ __forceinline__ uint32_t smem_u32(const void* p) {
    uint32_t a;
    asm("{ .reg .u64 t; cvta.to.shared.u64 t, %1; cvt.u32.u64 %0, t; }" : "=r"(a) : "l"(p));
    return a;
}
__device__ __forceinline__ void cp16(uint32_t saddr, const void* g) {
    asm volatile("cp.async.cg.shared.global [%0], [%1], 16;" :: "r"(saddr), "l"(g));
}
__device__ __forceinline__ void ldsm_x4(uint32_t r[4], uint32_t addr) {
    asm volatile("ldmatrix.sync.aligned.m8n8.x4.shared.b16 {%0,%1,%2,%3}, [%4];"
                 : "=r"(r[0]), "=r"(r[1]), "=r"(r[2]), "=r"(r[3]) : "r"(addr));
}
__device__ __forceinline__ void mma_f16(float c[4], const uint32_t a[4], uint32_t b0, uint32_t b1) {
    asm volatile(
        "mma.sync.aligned.m16n8k16.row.col.f32.f16.f16.f32 "
        "{%0,%1,%2,%3}, {%4,%5,%6,%7}, {%8,%9}, {%0,%1,%2,%3};"
        : "+f"(c[0]), "+f"(c[1]), "+f"(c[2]), "+f"(c[3])
        : "r"(a[0]), "r"(a[1]), "r"(a[2]), "r"(a[3]), "r"(b0), "r"(b1));
}
// pack two fp32 -> fp16x2 word
__device__ __forceinline__ uint32_t pack2h(float v0, float v1) {
    __half2 hp = __floats2half2_rn(v0, v1);
    return *(uint32_t*)&hp;
}

// ---------------- 1-term MMA pass, warp tile 16x64: D = A*W (A fp16-rounded) ----------------
template<int AO, int WO>
__device__ __forceinline__ void mma_pass1(
    uint32_t sb, uint32_t aoff_base, uint32_t axor, int acg,
    int wn, int bn_local, int bcg, float acc[8][4]) {
#pragma unroll
    for (int ks = 0; ks < 8; ks++) {
        const int kb = ks * 32;
        uint32_t ah[4];
        uint32_t a_addr = sb + aoff_base + (uint32_t)((kb + acg) ^ axor);
        ldsm_x4(ah, a_addr + AO);
#pragma unroll
        for (int p = 0; p < 4; p++) {
            const int nrow = wn * 64 + p * 16 + bn_local;
            uint32_t b_addr = sb + (uint32_t)(nrow * 256)
                            + (uint32_t)((kb + bcg) ^ ((nrow & 7) << 4));
            uint32_t bh[4];
            ldsm_x4(bh, b_addr + WO);
            mma_f16(acc[2 * p],     ah, bh[0], bh[1]);
            mma_f16(acc[2 * p + 1], ah, bh[2], bh[3]);
        }
    }
}

// ---------------- conv GEMM: M-tile 64, 256 thr, 48KB smem, fp16 out ----------------
#define SA_A 0
#define SW_W 16384
#define GEMM_SMEM 49152

__global__ void __launch_bounds__(256, 3) mma_gemm_h(
    const float* __restrict__ A,
    const uint4* __restrict__ Wt,
    __half* __restrict__ C,
    int M, int mode) {
    extern __shared__ char smem[];
    const uint32_t sb = smem_u32(smem);
    const int tid = threadIdx.x;
    const int lane = tid & 31;
    const int wid = tid >> 5;
    const int wm = wid & 3;     // 4 M-blocks of 16
    const int wn = wid >> 2;    // 2 N-blocks of 64
    const int blockRow = blockIdx.x * 64;

    // W image via cp.async: 2048 uint4, 8 iters
#pragma unroll
    for (int i = 0; i < 8; i++) {
        int c = tid + i * 256;
        int n = c >> 4;
        int kb = (c & 15) * 16;
        uint32_t off = (uint32_t)(n * 256) + (uint32_t)(kb ^ ((n & 7) << 4));
        cp16(sb + SW_W + off, &Wt[c]);
    }
    asm volatile("cp.async.commit_group;" ::: "memory");

    // A: 64 rows x 32 float4, convert fp32 -> fp16
#pragma unroll
    for (int i = 0; i < 8; i++) {
        int idx = tid + i * 256;
        int row = idx >> 5;
        int col = (idx & 31) * 4;
        int grow = blockRow + row;
        float4 v = make_float4(0.f, 0.f, 0.f, 0.f);
        if (grow < M) v = *(const float4*)&A[grow * HH + col];
        if (mode & 32) { v.x = lrelu(v.x); v.y = lrelu(v.y); v.z = lrelu(v.z); v.w = lrelu(v.w); }
        uint32_t h0 = pack2h(v.x, v.y);
        uint32_t h1 = pack2h(v.z, v.w);
        uint32_t off = (uint32_t)(row * 256) + (uint32_t)((col * 2) ^ ((row & 7) << 4));
        *(uint2*)(smem + SA_A + off) = make_uint2(h0, h1);
    }
    asm volatile("cp.async.wait_group 0;" ::: "memory");
    __syncthreads();

    float acc[8][4];
#pragma unroll
    for (int j = 0; j < 8; j++)
#pragma unroll
        for (int q = 0; q < 4; q++) acc[j][q] = 0.f;

    const int arow = wm * 16 + (lane & 15);
    const int acg = (lane >> 4) * 16;
    const uint32_t aoff_base = (uint32_t)(arow * 256);
    const uint32_t axor = (uint32_t)((arow & 7) << 4);
    const int bn_local = (lane & 7) + ((lane >> 4) & 1) * 8;
    const int bcg = ((lane >> 3) & 1) * 16;

    mma_pass1<SA_A, SW_W>(sb, aoff_base, axor, acg, wn, bn_local, bcg, acc);

    const int g = lane >> 2, t = lane & 3;
    int rr0 = blockRow + wm * 16 + g;
#pragma unroll
    for (int h = 0; h < 2; h++) {
        int row = rr0 + h * 8;
        if (row >= M) continue;
#pragma unroll
        for (int j = 0; j < 8; j++) {
            int col = wn * 64 + j * 8 + t * 2;
            *(__half2*)&C[row * HH + col] =
                __floats2half2_rn(acc[j][h * 2 + 0], acc[j][h * 2 + 1]);
        }
    }
}

// ---------------- 4-layer fused MLP: 256 thr, 48KB, W region reloaded per layer ----------------
#define G_A 0
#define G_W 16384
#define G_SMEM 49152

struct MLP4Args {
    const uint4* w[4];
    const float* b[4];
};

__global__ void __launch_bounds__(256, 3) mlp4(
    const float* __restrict__ A,     // h2 (also the residual)
    MLP4Args args,
    const float* __restrict__ gen,
    float* __restrict__ C,
    int M) {
    extern __shared__ char smem[];
    const uint32_t sb = smem_u32(smem);
    const int tid = threadIdx.x;
    const int lane = tid & 31;
    const int wid = tid >> 5;
    const int wm = wid & 3;
    const int wn = wid >> 2;
    const int blockRow = blockIdx.x * 64;

    // W0 via cp.async
#pragma unroll
    for (int i = 0; i < 8; i++) {
        int c = tid + i * 256;
        int n = c >> 4;
        int kb = (c & 15) * 16;
        uint32_t off = (uint32_t)(n * 256) + (uint32_t)(kb ^ ((n & 7) << 4));
        cp16(sb + G_W + off, &args.w[0][c]);
    }
    asm volatile("cp.async.commit_group;" ::: "memory");

    // A: 64 rows x 32 float4, convert to fp16
#pragma unroll
    for (int i = 0; i < 8; i++) {
        int idx = tid + i * 256;
        int row = idx >> 5;
        int col = (idx & 31) * 4;
        int grow = blockRow + row;
        float4 v = make_float4(0.f, 0.f, 0.f, 0.f);
        if (grow < M) v = *(const float4*)&A[grow * HH + col];
        uint32_t h0 = pack2h(v.x, v.y);
        uint32_t h1 = pack2h(v.z, v.w);
        uint32_t off = (uint32_t)(row * 256) + (uint32_t)((col * 2) ^ ((row & 7) << 4));
        *(uint2*)(smem + G_A + off) = make_uint2(h0, h1);
    }
    asm volatile("cp.async.wait_group 0;" ::: "memory");
    __syncthreads();

    const int arow = wm * 16 + (lane & 15);
    const int acg = (lane >> 4) * 16;
    const uint32_t aoff_base = (uint32_t)(arow * 256);
    const uint32_t axor = (uint32_t)((arow & 7) << 4);
    const int bn_local = (lane & 7) + ((lane >> 4) & 1) * 8;
    const int bcg = ((lane >> 3) & 1) * 16;
    const int g = lane >> 2, t = lane & 3;

    float acc[8][4];

#pragma unroll
    for (int layer = 0; layer < 4; layer++) {
#pragma unroll
        for (int j = 0; j < 8; j++)
#pragma unroll
            for (int q = 0; q < 4; q++) acc[j][q] = 0.f;
        mma_pass1<G_A, G_W>(sb, aoff_base, axor, acg, wn, bn_local, bcg, acc);
        __syncthreads();   // all warps done reading W[layer] and A smem

        if (layer < 3) {
            // prefetch next layer's weights over the W region
#pragma unroll
            for (int i = 0; i < 8; i++) {
                int c = tid + i * 256;
                int n = c >> 4;
                int kb = (c & 15) * 16;
                uint32_t off = (uint32_t)(n * 256) + (uint32_t)(kb ^ ((n & 7) << 4));
                cp16(sb + G_W + off, &args.w[layer + 1][c]);
            }
            asm volatile("cp.async.commit_group;" ::: "memory");
        }

        const float* bias = args.b[layer];
        if (layer == 3) {
            // final: leaky(acc + b) -> gmem
#pragma unroll
            for (int h = 0; h < 2; h++) {
                int row = blockRow + wm * 16 + g + h * 8;
                if (row >= M) continue;
#pragma unroll
                for (int j = 0; j < 8; j++) {
                    int col = wn * 64 + j * 8 + t * 2;
                    float v0 = lrelu(acc[j][h * 2 + 0] + bias[col]);
                    float v1 = lrelu(acc[j][h * 2 + 1] + bias[col + 1]);
                    *(float2*)&C[row * HH + col] = make_float2(v0, v1);
                }
            }
        } else {
            // intermediate epilogue -> back into A smem as fp16
#pragma unroll
            for (int h = 0; h < 2; h++) {
                int lrow = wm * 16 + g + h * 8;
                int grow = blockRow + lrow;
#pragma unroll
                for (int j = 0; j < 8; j++) {
                    int col = wn * 64 + j * 8 + t * 2;
                    float v0 = acc[j][h * 2 + 0] + bias[col];
                    float v1 = acc[j][h * 2 + 1] + bias[col + 1];
                    if (layer == 1) {
                        float2 rv = (grow < M) ? *(const float2*)&A[grow * HH + col]
                                               : make_float2(0.f, 0.f);
                        v0 = lrelu(v0 + rv.x);
                        v1 = lrelu(v1 + rv.y);
                        float2 gv = (grow < M) ? *(const float2*)&gen[grow * HH + col]
                                               : make_float2(0.f, 0.f);
                        v0 = 0.5f * v0 + 0.5f * gv.x;
                        v1 = 0.5f * v1 + 0.5f * gv.y;
                    } else {
                        v0 = lrelu(v0);
                        v1 = lrelu(v1);
                    }
                    uint32_t hw = pack2h(v0, v1);
                    uint32_t off = (uint32_t)(lrow * 256) + (uint32_t)((col * 2) ^ ((lrow & 7) << 4));
                    *(uint32_t*)(smem + G_A + off) = hw;
                }
            }
            asm volatile("cp.async.wait_group 0;" ::: "memory");
            __syncthreads();
        }
    }
}

// ---------------- launch ----------------
extern "C" void kernel_launch(void* const* d_in, const int* in_sizes, int n_in,
                              void* d_out, int out_size) {
    const float* x   = (const float*)d_in[0];
    const int*   ei  = (const int*)d_in[1];
    const float* gen = (const float*)d_in[2];
    const float* Wc1 = (const float*)d_in[3];
    const float* bc1 = (const float*)d_in[4];
    const float* Wc2 = (const float*)d_in[5];
    const float* bc2 = (const float*)d_in[6];
    const float* Wm1 = (const float*)d_in[7];
    const float* bm1 = (const float*)d_in[8];
    const float* Wm2 = (const float*)d_in[9];
    const float* bm2 = (const float*)d_in[10];
    const float* Wp1 = (const float*)d_in[11];
    const float* bp1 = (const float*)d_in[12];
    const float* Wp2 = (const float*)d_in[13];
    const float* bp2 = (const float*)d_in[14];

    const int* src = ei;
    const int* dst = ei + EE;

    float *bufA, *bufB, *bufC;
    __half* wh;
    int* cntp;
    cudaGetSymbolAddress((void**)&bufA, g_bufA);
    cudaGetSymbolAddress((void**)&bufB, g_bufB);
    cudaGetSymbolAddress((void**)&bufC, g_bufC);
    cudaGetSymbolAddress((void**)&wh, g_wh);
    cudaGetSymbolAddress((void**)&cntp, g_cnt);

    static bool s_init = false;
    static cudaStream_t s_side;
    static cudaEvent_t ev_fork, ev_join;
    if (!s_init) {
        cudaStreamCreateWithFlags(&s_side, cudaStreamNonBlocking);
        cudaEventCreateWithFlags(&ev_fork, cudaEventDisableTiming);
        cudaEventCreateWithFlags(&ev_join, cudaEventDisableTiming);
        cudaFuncSetAttribute(mma_gemm_h, cudaFuncAttributeMaxDynamicSharedMemorySize, GEMM_SMEM);
        cudaFuncSetAttribute(mlp4, cudaFuncAttributeMaxDynamicSharedMemorySize, G_SMEM);
        s_init = true;
    }

    const int gE4 = (EE / 4 + 255) / 256;
    const int gN = (NN + 255) / 256;
    const int gGat = (NN * 32 + 255) / 256;   // warp per node
    const int gG = (NN + 63) / 64;            // M=64 tiles

    const uint4* w4 = (const uint4*)wh;
    const int WSTEP = HH * HH / 8;            // uint4 per fp16 layer image
    __half* hbuf = (__half*)bufA;

    WPtrs wp;
    wp.p[0] = Wc1; wp.p[1] = Wc2; wp.p[2] = Wm1;
    wp.p[3] = Wm2; wp.p[4] = Wp1; wp.p[5] = Wp2;
    dim3 wgrid((HH * HH + 255) / 256, 6);

    // fork: CSR build on side stream (hidden under wconv + conv1)
    cudaMemsetAsync(cntp, 0, NN * sizeof(int));
    cudaEventRecord(ev_fork, 0);
    cudaStreamWaitEvent(s_side, ev_fork, 0);
    fill_kernel<<<gE4, 256, 0, s_side>>>(src, dst);
    dinv_kernel<<<gN, 256, 0, s_side>>>();
    cudaEventRecord(ev_join, s_side);

    // main: weights + conv1 GEMM (independent of CSR)
    wconv_all<<<wgrid, 256>>>(wp);
    mma_gemm_h<<<gG, 256, GEMM_SMEM>>>(x, w4, hbuf, NN, 0);

    // join: gather needs CSR
    cudaStreamWaitEvent(0, ev_join, 0);
    gather_kernel<<<gGat, 256>>>(hbuf, bc1, nullptr, bufB);

    // conv2
    mma_gemm_h<<<gG, 256, GEMM_SMEM>>>(bufB, w4 + WSTEP, hbuf, NN, 32);
    gather_kernel<<<gGat, 256>>>(hbuf, bc2, bufB, bufC);

    // 4-layer fused MLP + proj -> out
    MLP4Args ma;
    ma.w[0] = w4 + 2 * WSTEP; ma.b[0] = bm1;
    ma.w[1] = w4 + 3 * WSTEP; ma.b[1] = bm2;
    ma.w[2] = w4 + 4 * WSTEP; ma.b[2] = bp1;
    ma.w[3] = w4 + 5 * WSTEP; ma.b[3] = bp2;
    mlp4<<<gG, 256, G_SMEM>>>(bufC, ma, gen, (float*)d_out, NN);
}